// round 10
// baseline (speedup 1.0000x reference)
#include <cuda_runtime.h>
#include <cstdint>

typedef unsigned long long ULL;

// Scaled + transposed weights: layout [c][ky][kx][oc], 32*3*3*32 = 9216 floats.
__device__ float g_ws[9216];

// ---------------------------------------------------------------------------
// Kernel 1: sigma = max(1, s1/2).
// G = W W^T built from a transposed, bank-padded copy of W (conflict-free).
// 14x repeated squaring with per-thread redundant trace normalization,
// then Rayleigh quotient against the original G. Writes w_bar/sigma to g_ws.
// ---------------------------------------------------------------------------
#define WT_STRIDE 33

__global__ void sigma_kernel(const float* __restrict__ w_bar) {
    __shared__ float Wt[288 * WT_STRIDE];  // W^T padded; reused as ping-pong
    __shared__ float G0[1024];             // original G, preserved
    __shared__ float s_inv;

    int tid = threadIdx.x;

    // Load W transposed: Wt[k][i] = w_bar[i*288 + k], stride 33 (conflict-free)
    for (int m = tid; m < 9216; m += 256) {
        int i = m / 288;
        int k = m - i * 288;
        Wt[k * WT_STRIDE + i] = w_bar[m];
    }
    __syncthreads();

    // G0[i][j] = sum_k Wt[k][i] * Wt[k][j]  (broadcast + consecutive reads)
    for (int e = tid; e < 1024; e += 256) {
        int i = e >> 5, j = e & 31;
        float s = 0.f;
        #pragma unroll 4
        for (int k = 0; k < 288; ++k)
            s += Wt[k * WT_STRIDE + i] * Wt[k * WT_STRIDE + j];
        G0[e] = s;
    }
    __syncthreads();

    // Ping-pong buffers alias the (now free) Wt region.
    float* bufA = Wt;
    float* bufB = Wt + 1024;

    const float* cur = G0;
    float* nxt = bufA;
    for (int it = 0; it < 14; ++it) {
        // trace, computed redundantly by every thread (broadcast LDS, no sync)
        float tr = 0.f;
        #pragma unroll
        for (int d = 0; d < 32; ++d) tr += cur[d * 33];
        float inv = 1.0f / fmaxf(tr, 1e-30f);
        float inv2 = inv * inv;

        for (int e = tid; e < 1024; e += 256) {
            int i = e >> 5, j = e & 31;
            const float* ri = cur + i * 32;
            float s = 0.f;
            #pragma unroll
            for (int k = 0; k < 32; ++k) s += ri[k] * cur[k * 32 + j];
            nxt[e] = s * inv2;
        }
        __syncthreads();
        cur = nxt;
        nxt = (nxt == bufA) ? bufB : bufA;
    }

    // Rayleigh quotient with original G on v = dominant column of cur.
    if (tid < 32) {
        float d = cur[tid * 33];
        int jbest = tid;
        #pragma unroll
        for (int off = 16; off > 0; off >>= 1) {
            float od = __shfl_xor_sync(0xffffffffu, d, off);
            int   oj = __shfl_xor_sync(0xffffffffu, jbest, off);
            if (od > d) { d = od; jbest = oj; }
        }
        jbest = __shfl_sync(0xffffffffu, jbest, 0);

        float v = cur[tid * 32 + jbest];          // lane i holds v_i
        float gv = 0.f;
        const float* gi = G0 + tid * 32;
        #pragma unroll
        for (int j = 0; j < 32; ++j)
            gv += gi[j] * __shfl_sync(0xffffffffu, v, j);

        float num = v * gv, den = v * v;
        #pragma unroll
        for (int off = 16; off > 0; off >>= 1) {
            num += __shfl_xor_sync(0xffffffffu, num, off);
            den += __shfl_xor_sync(0xffffffffu, den, off);
        }
        if (tid == 0) {
            float lambda1 = num / fmaxf(den, 1e-30f);  // = s1^2
            float s1 = sqrtf(fmaxf(lambda1, 0.f));
            float sigma = fmaxf(1.0f, 0.5f * s1);
            s_inv = 1.0f / sigma;
        }
    }
    __syncthreads();

    float invs = s_inv;
    // transpose [oc][c][ky][kx] -> [c][ky][kx][oc] while scaling (re-read gmem)
    for (int i = tid; i < 9216; i += 256) {
        int oc  = i / 288;
        int rem = i - oc * 288;    // c*9 + ky*3 + kx
        g_ws[rem * 32 + oc] = w_bar[i] * invs;
    }
}

// ---------------------------------------------------------------------------
// Packed f32x2 helpers
// ---------------------------------------------------------------------------
__device__ __forceinline__ ULL dupf(float x) {
    ULL r;
    asm("mov.b64 %0, {%1, %1};" : "=l"(r) : "f"(x));
    return r;
}
__device__ __forceinline__ ULL pack2(float lo, float hi) {
    ULL r;
    asm("mov.b64 %0, {%1, %2};" : "=l"(r) : "f"(lo), "f"(hi));
    return r;
}
__device__ __forceinline__ void fma2(ULL& d, ULL a, ULL b) {
    asm("fma.rn.f32x2 %0, %1, %2, %0;" : "+l"(d) : "l"(a), "l"(b));
}

// ---------------------------------------------------------------------------
// Kernel 2: direct 3x3 conv, pad 1. Tile = 16x16 pixels. Channels staged in
// FOUR quarters of 8 channels, cp.async double-buffered so the gmem staging
// of quarter q+1 overlaps compute of quarter q.
// smem: xs[2][8][18][20] (5760 f) + ws[9216 f] = 59904 B -> 3 CTAs/SM.
// 256 threads; each thread: 4 px x 8 oc via f32x2.
// ---------------------------------------------------------------------------
#define XS_STRIDE 20
#define XS_CH     (18 * XS_STRIDE)            // 360
#define QBUF      (8 * XS_CH)                 // 2880 floats per quarter buffer
#define SMEM_BYTES ((2 * QBUF + 9216) * 4)    // 59904

extern __shared__ float s_mem[];

__device__ __forceinline__ void stage_quarter(float* dst, const float* xq,
                                              int gy0, int gx0, int tid) {
    #pragma unroll 1
    for (int i = tid; i < 8 * 324; i += 256) {
        int c   = i / 324;
        int rem = i - c * 324;
        int r   = rem / 18;
        int col = rem - r * 18;
        int gy = gy0 + r, gx = gx0 + col;
        bool ok = ((unsigned)gy < 256u) && ((unsigned)gx < 256u);
        // clamp so the address is always valid; src-size=0 zero-fills
        int cgy = min(max(gy, 0), 255), cgx = min(max(gx, 0), 255);
        const float* src = xq + c * 65536 + cgy * 256 + cgx;
        uint32_t saddr = (uint32_t)__cvta_generic_to_shared(
            dst + c * XS_CH + r * XS_STRIDE + col);
        int sz = ok ? 4 : 0;
        asm volatile("cp.async.ca.shared.global [%0], [%1], 4, %2;"
                     :: "r"(saddr), "l"(src), "r"(sz) : "memory");
    }
}

__global__ __launch_bounds__(256, 3)
void conv_kernel(const float* __restrict__ x,
                 const float* __restrict__ bias,
                 float* __restrict__ out) {
    float* xs  = s_mem;                  // [2][QBUF]
    float* wss = s_mem + 2 * QBUF;

    int tid = threadIdx.x;
    int tx = blockIdx.x, ty = blockIdx.y, n = blockIdx.z;

    // stage weights (plain loads; published by the first __syncthreads)
    for (int i = tid; i < 9216; i += 256) wss[i] = g_ws[i];

    const float* xn = x + (size_t)n * (32u * 256u * 256u);
    int gy0 = ty * 16 - 1, gx0 = tx * 16 - 1;

    // lane map: ocg = tid&3 (8 oc each); slot -> row (0..15), col quad.
    int ocg    = tid & 3;
    int slot   = tid >> 2;
    int row    = slot >> 2;
    int cb     = (slot & 3) * 4;
    int ocbase = ocg * 8;

    // accumulators: acc[px][ocpair], init with bias
    ULL acc[4][4];
    #pragma unroll
    for (int p = 0; p < 4; ++p) {
        ULL b = pack2(bias[ocbase + 2 * p], bias[ocbase + 2 * p + 1]);
        acc[0][p] = b; acc[1][p] = b; acc[2][p] = b; acc[3][p] = b;
    }

    const float* wb = wss + ocbase;   // [c][ky][kx][oc], oc offset baked in

    // prefetch quarter 0
    stage_quarter(xs, xn, gy0, gx0, tid);
    asm volatile("cp.async.commit_group;" ::: "memory");

    #pragma unroll 1
    for (int q = 0; q < 4; ++q) {
        if (q < 3) {
            stage_quarter(xs + ((q + 1) & 1) * QBUF,
                          xn + (size_t)(q + 1) * 8u * 65536u, gy0, gx0, tid);
            asm volatile("cp.async.commit_group;" ::: "memory");
            asm volatile("cp.async.wait_group 1;" ::: "memory");
        } else {
            asm volatile("cp.async.wait_group 0;" ::: "memory");
        }
        __syncthreads();   // quarter q staged (also publishes weights at q=0)

        const float* xq = xs + (q & 1) * QBUF;
        const float* wh = wb + q * 8 * 288;
        #pragma unroll 1
        for (int c = 0; c < 8; ++c) {
            const float* xc = xq + c * XS_CH;
            const float* wc = wh + c * 288;
            #pragma unroll
            for (int ky = 0; ky < 3; ++ky) {
                const float* xr = xc + (row + ky) * XS_STRIDE + cb;
                float4 xa = *(const float4*)xr;          // x[0..3]
                float2 xb = *(const float2*)(xr + 4);    // x[4..5]
                ULL xd[6];
                xd[0] = dupf(xa.x); xd[1] = dupf(xa.y); xd[2] = dupf(xa.z);
                xd[3] = dupf(xa.w); xd[4] = dupf(xb.x); xd[5] = dupf(xb.y);

                const float* wk = wc + ky * 96;
                #pragma unroll
                for (int kx = 0; kx < 3; ++kx) {
                    ulonglong2 wA = *(const ulonglong2*)(wk + kx * 32);
                    ulonglong2 wB = *(const ulonglong2*)(wk + kx * 32 + 4);
                    #pragma unroll
                    for (int j = 0; j < 4; ++j) {
                        fma2(acc[j][0], xd[kx + j], wA.x);
                        fma2(acc[j][1], xd[kx + j], wA.y);
                        fma2(acc[j][2], xd[kx + j], wB.x);
                        fma2(acc[j][3], xd[kx + j], wB.y);
                    }
                }
            }
        }
        __syncthreads();   // done reading buffer (q&1) before it is re-filled
    }

    // epilogue: for each oc, 4 consecutive pixels -> one STG.128
    int gy = ty * 16 + row;
    int gx = tx * 16 + cb;
    float* outp = out + (size_t)n * 32u * 65536u + gy * 256 + gx;
    #pragma unroll
    for (int p = 0; p < 4; ++p) {
        #pragma unroll
        for (int h = 0; h < 2; ++h) {
            int oc = ocbase + 2 * p + h;
            float4 o;
            o.x = ((const float*)&acc[0][p])[h];
            o.y = ((const float*)&acc[1][p])[h];
            o.z = ((const float*)&acc[2][p])[h];
            o.w = ((const float*)&acc[3][p])[h];
            *(float4*)(outp + (size_t)oc * 65536u) = o;
        }
    }
}

// ---------------------------------------------------------------------------
// Launch
// ---------------------------------------------------------------------------
extern "C" void kernel_launch(void* const* d_in, const int* in_sizes, int n_in,
                              void* d_out, int out_size) {
    const float* x    = nullptr;
    const float* wbar = nullptr;
    const float* bias = nullptr;
    for (int i = 0; i < n_in; ++i) {
        if (in_sizes[i] == 9216)      wbar = (const float*)d_in[i];
        else if (in_sizes[i] == 32)   bias = (const float*)d_in[i];
        else                          x    = (const float*)d_in[i];
    }

    sigma_kernel<<<1, 256>>>(wbar);

    cudaFuncSetAttribute(conv_kernel,
                         cudaFuncAttributeMaxDynamicSharedMemorySize,
                         SMEM_BYTES);
    dim3 grid(16, 16, 32);   // x-tiles, y-tiles, batch
    conv_kernel<<<grid, 256, SMEM_BYTES>>>(x, bias, (float*)d_out);
}